// round 16
// baseline (speedup 1.0000x reference)
#include <cuda_runtime.h>
#include <cuda_bf16.h>
#include <math.h>
#include <stdint.h>

// Problem constants
#define S_LEN 2048
#define BATCH 4
#define HDIM  1024
#define NHEAD 16
#define DKDIM 64
#define MROWS (S_LEN * BATCH)   // 8192

// ---------------------------------------------------------------------------
// Scratch (static device globals)
// ---------------------------------------------------------------------------
__device__ __nv_bfloat16 g_in_hi[3][(size_t)MROWS * HDIM];  // split(query/key/value)
__device__ __nv_bfloat16 g_in_lo[3][(size_t)MROWS * HDIM];
__device__ __nv_bfloat16 g_w_hi[4][(size_t)HDIM * HDIM];    // split(Wq/Wk/Wv/Wo)
__device__ __nv_bfloat16 g_w_lo[4][(size_t)HDIM * HDIM];
__device__ __nv_bfloat16 g_Qh[(size_t)MROWS * HDIM];        // projected, split
__device__ __nv_bfloat16 g_Ql[(size_t)MROWS * HDIM];
__device__ __nv_bfloat16 g_Kh[(size_t)MROWS * HDIM];
__device__ __nv_bfloat16 g_Kl[(size_t)MROWS * HDIM];
__device__ __nv_bfloat16 g_Vh[(size_t)MROWS * HDIM];
__device__ __nv_bfloat16 g_Vl[(size_t)MROWS * HDIM];
__device__ __nv_bfloat16 g_Ah[(size_t)MROWS * HDIM];        // attention out, split
__device__ __nv_bfloat16 g_Al[(size_t)MROWS * HDIM];
__device__ int g_len[BATCH];

// ---------------------------------------------------------------------------
// PTX helpers (non-'a' features only: ldmatrix / mma.sync / cp.async)
// ---------------------------------------------------------------------------
__device__ __forceinline__ uint32_t smem_u32(const void* p) {
    uint32_t a;
    asm("{ .reg .u64 t; cvta.to.shared.u64 t, %1; cvt.u32.u64 %0, t; }"
        : "=r"(a) : "l"(p));
    return a;
}

__device__ __forceinline__ void cp16(uint32_t s, const void* g) {
    asm volatile("cp.async.cg.shared.global [%0], [%1], 16;" :: "r"(s), "l"(g));
}

__device__ __forceinline__ void ldsm4(uint32_t* r, uint32_t addr) {
    asm volatile("ldmatrix.sync.aligned.m8n8.x4.shared.b16 {%0,%1,%2,%3}, [%4];"
                 : "=r"(r[0]), "=r"(r[1]), "=r"(r[2]), "=r"(r[3]) : "r"(addr));
}

__device__ __forceinline__ void ldsm4t(uint32_t* r, uint32_t addr) {
    asm volatile("ldmatrix.sync.aligned.m8n8.x4.trans.shared.b16 {%0,%1,%2,%3}, [%4];"
                 : "=r"(r[0]), "=r"(r[1]), "=r"(r[2]), "=r"(r[3]) : "r"(addr));
}

__device__ __forceinline__ void mma16816(float* d, const uint32_t* a,
                                         uint32_t b0, uint32_t b1) {
    asm volatile(
        "mma.sync.aligned.m16n8k16.row.col.f32.bf16.bf16.f32 "
        "{%0,%1,%2,%3}, {%4,%5,%6,%7}, {%8,%9}, {%0,%1,%2,%3};"
        : "+f"(d[0]), "+f"(d[1]), "+f"(d[2]), "+f"(d[3])
        : "r"(a[0]), "r"(a[1]), "r"(a[2]), "r"(a[3]), "r"(b0), "r"(b1));
}

// split pair of floats into bf16x2 hi + lo words
__device__ __forceinline__ void split2(float a, float b, uint32_t& hi, uint32_t& lo) {
    __nv_bfloat16 ha = __float2bfloat16(a);
    __nv_bfloat16 hb = __float2bfloat16(b);
    float ra = a - __bfloat162float(ha);
    float rb = b - __bfloat162float(hb);
    __nv_bfloat162 th = __halves2bfloat162(ha, hb);
    __nv_bfloat162 tl = __halves2bfloat162(__float2bfloat16(ra), __float2bfloat16(rb));
    hi = *(uint32_t*)&th;
    lo = *(uint32_t*)&tl;
}

// ---------------------------------------------------------------------------
// Per-batch valid length
// ---------------------------------------------------------------------------
__global__ void __launch_bounds__(512)
len_kernel(const float* __restrict__ key)
{
    __shared__ int sh[512];
    int b = blockIdx.x;
    int cnt = 0;
    for (int s = threadIdx.x; s < S_LEN; s += 512) {
        float4 v = *(const float4*)(key + (size_t)(s * BATCH + b) * HDIM);
        cnt += (v.x != 0.0f || v.y != 0.0f || v.z != 0.0f || v.w != 0.0f) ? 1 : 0;
    }
    sh[threadIdx.x] = cnt;
    __syncthreads();
    for (int o = 256; o > 0; o >>= 1) {
        if (threadIdx.x < o) sh[threadIdx.x] += sh[threadIdx.x + o];
        __syncthreads();
    }
    if (threadIdx.x == 0) g_len[b] = sh[0];
}

// ---------------------------------------------------------------------------
// fp32 -> bf16 hi/lo splits (fused multi-tensor launches)
// ---------------------------------------------------------------------------
__device__ __forceinline__ void split_store(const float* src, __nv_bfloat16* hi,
                                            __nv_bfloat16* lo, size_t i)
{
    float4 v = *(const float4*)(src + i);
    uint32_t h0, l0, h1, l1;
    split2(v.x, v.y, h0, l0);
    split2(v.z, v.w, h1, l1);
    uint32_t* hp = (uint32_t*)(hi + i);
    uint32_t* lp = (uint32_t*)(lo + i);
    hp[0] = h0; hp[1] = h1;
    lp[0] = l0; lp[1] = l1;
}

__global__ void __launch_bounds__(256)
convert_in_kernel(const float* __restrict__ q, const float* __restrict__ k,
                  const float* __restrict__ v)
{
    int t = blockIdx.y;
    const float* src = (t == 0) ? q : (t == 1) ? k : v;
    size_t i = ((size_t)blockIdx.x * 256 + threadIdx.x) * 4;
    split_store(src, g_in_hi[t], g_in_lo[t], i);
}

__global__ void __launch_bounds__(256)
convert_w_kernel(const float* __restrict__ wq, const float* __restrict__ wk,
                 const float* __restrict__ wv, const float* __restrict__ wo)
{
    int t = blockIdx.y;
    const float* src = (t == 0) ? wq : (t == 1) ? wk : (t == 2) ? wv : wo;
    size_t i = ((size_t)blockIdx.x * 256 + threadIdx.x) * 4;
    split_store(src, g_w_hi[t], g_w_lo[t], i);
}

// ---------------------------------------------------------------------------
// HMMA GEMM core (NT): acc = sum_k A[m][k] * W[n][k], bf16 hi/lo split
// (D += Ah*Wh + Ah*Wl + Al*Wh).
// CTA tile 128x256, 8 warps (2x4), warp tile 64x64 (high MMA:ldsm ratio).
// XOR-swizzled SMEM, 3-stage cp.async pipeline, 1 sync/chunk, 1 CTA/SM.
// ---------------------------------------------------------------------------
#define ATILEB 8192                     // 128 rows x 64B
#define BTILEB 16384                    // 256 rows x 64B
#define STAGEB (2 * ATILEB + 2 * BTILEB)   // 49152: Ah, Al, Bh, Bl
#define GEMM_SMEM_BYTES (3 * STAGEB)    // 147456

// swizzled byte offset of 16B piece p (0..3) in row r (64B rows)
__device__ __forceinline__ uint32_t gswz(uint32_t r, uint32_t p) {
    return r * 64 + ((p ^ ((r >> 1) & 3)) << 4);
}

__device__ __forceinline__ void gemm_core(
    const __nv_bfloat16* Ahi, const __nv_bfloat16* Alo,
    const __nv_bfloat16* Bhi, const __nv_bfloat16* Blo,
    int m0, int n0, uint32_t tb, float acc[4][8][4])
{
    int tid = threadIdx.x;
    int wid = tid >> 5;
    int lane = tid & 31;
    int wm = (wid >> 2) * 64;           // 2 warp rows
    int wn = (wid & 3) * 64;            // 4 warp cols

    const char* gA[2];
    const char* gB[2];
    gA[0] = (const char*)(Ahi + (size_t)m0 * HDIM);
    gA[1] = (const char*)(Alo + (size_t)m0 * HDIM);
    gB[0] = (const char*)(Bhi + (size_t)n0 * HDIM);
    gB[1] = (const char*)(Blo + (size_t)n0 * HDIM);

#pragma unroll
    for (int i = 0; i < 4; i++)
#pragma unroll
        for (int j = 0; j < 8; j++)
#pragma unroll
            for (int r = 0; r < 4; r++) acc[i][j][r] = 0.0f;

    const int NC = HDIM / 32;           // 32 chunks

    auto load_stage = [&](int stage, int c) {
        uint32_t sbase = tb + stage * STAGEB;
        int kbyte = c * 64;
        // A tiles: 1024 pieces (2 tensors x 128 rows x 4)
#pragma unroll
        for (int j = 0; j < 4; j++) {
            int idx = tid + j * 256;    // 0..1023
            int t = idx >> 9;
            uint32_t r = (idx >> 2) & 127;
            uint32_t p = idx & 3;
            cp16(sbase + t * ATILEB + gswz(r, p),
                 gA[t] + (size_t)r * 2048 + kbyte + p * 16);
        }
        // B tiles: 2048 pieces (2 tensors x 256 rows x 4)
#pragma unroll
        for (int j = 0; j < 8; j++) {
            int idx = tid + j * 256;    // 0..2047
            int t = idx >> 10;
            uint32_t r = (idx >> 2) & 255;
            uint32_t p = idx & 3;
            cp16(sbase + 2 * ATILEB + t * BTILEB + gswz(r, p),
                 gB[t] + (size_t)r * 2048 + kbyte + p * 16);
        }
        asm volatile("cp.async.commit_group;");
    };

    load_stage(0, 0);
    load_stage(1, 1);

    int stage = 0, nstage = 2;
    for (int c = 0; c < NC; c++) {
        if (c < NC - 1) {
            asm volatile("cp.async.wait_group 1;" ::: "memory");
        } else {
            asm volatile("cp.async.wait_group 0;" ::: "memory");
        }
        __syncthreads();                 // stage c visible; oldest stage free
        if (c + 2 < NC)
            load_stage(nstage, c + 2);

        uint32_t abase = tb + stage * STAGEB;
        uint32_t bbase = abase + 2 * ATILEB;
#pragma unroll
        for (int kh = 0; kh < 2; kh++) {
            uint32_t p = (uint32_t)(kh * 2 + (lane >> 4));
            uint32_t bh[4][4], bl[4][4];
#pragma unroll
            for (int j = 0; j < 4; j++) {
                uint32_t r = (uint32_t)(wn + j * 16 + (lane & 15));
                uint32_t off = gswz(r, p);
                ldsm4(bh[j], bbase + off);
                ldsm4(bl[j], bbase + BTILEB + off);
            }
#pragma unroll
            for (int i = 0; i < 4; i++) {
                uint32_t r = (uint32_t)(wm + i * 16 + (lane & 15));
                uint32_t off = gswz(r, p);
                uint32_t ah[4], al[4];
                ldsm4(ah, abase + off);
                ldsm4(al, abase + ATILEB + off);
#pragma unroll
                for (int jn = 0; jn < 8; jn++) {
                    int j = jn >> 1, h = jn & 1;
                    mma16816(acc[i][jn], ah, bh[j][h], bh[j][h + 2]);
                    mma16816(acc[i][jn], ah, bl[j][h], bl[j][h + 2]);
                    mma16816(acc[i][jn], al, bh[j][h], bh[j][h + 2]);
                }
            }
        }
        stage = (stage == 2) ? 0 : stage + 1;
        nstage = (nstage == 2) ? 0 : nstage + 1;
    }
}

// ---- QKV projections fused (grid z = 0/1/2), split bf16 output ----
__global__ void __launch_bounds__(256, 1)
qkv_gemm_kernel()
{
    extern __shared__ char smem[];
    uint32_t tb = smem_u32(smem);
    int z = blockIdx.z;
    int m0 = blockIdx.y * 128;
    int n0 = blockIdx.x * 256;
    float alpha = (z == 0) ? 0.125f : 1.0f;   // 1/sqrt(DK) folded into Q

    float acc[4][8][4];
    gemm_core(g_in_hi[z], g_in_lo[z], g_w_hi[z], g_w_lo[z], m0, n0, tb, acc);

    __nv_bfloat16* Ohi = (z == 0) ? g_Qh : (z == 1) ? g_Kh : g_Vh;
    __nv_bfloat16* Olo = (z == 0) ? g_Ql : (z == 1) ? g_Kl : g_Vl;

    int tid = threadIdx.x;
    int wid = tid >> 5;
    int lane = tid & 31;
    int wm = (wid >> 2) * 64;
    int wn = (wid & 3) * 64;
    int group = lane >> 2, tig = lane & 3;
#pragma unroll
    for (int i = 0; i < 4; i++) {
#pragma unroll
        for (int jn = 0; jn < 8; jn++) {
            int row = m0 + wm + i * 16 + group;
            int col = n0 + wn + jn * 8 + tig * 2;
            uint32_t h0, l0, h1, l1;
            split2(alpha * acc[i][jn][0], alpha * acc[i][jn][1], h0, l0);
            split2(alpha * acc[i][jn][2], alpha * acc[i][jn][3], h1, l1);
            size_t o0 = (size_t)row * HDIM + col;
            size_t o1 = (size_t)(row + 8) * HDIM + col;
            *(uint32_t*)(Ohi + o0) = h0;
            *(uint32_t*)(Olo + o0) = l0;
            *(uint32_t*)(Ohi + o1) = h1;
            *(uint32_t*)(Olo + o1) = l1;
        }
    }
}

// ---- output projection: A = attention (g_Ah/g_Al), W = Wo, fp32 out ----
__global__ void __launch_bounds__(256, 1)
wo_gemm_kernel(float* __restrict__ C)
{
    extern __shared__ char smem[];
    uint32_t tb = smem_u32(smem);
    int m0 = blockIdx.y * 128;
    int n0 = blockIdx.x * 256;

    float acc[4][8][4];
    gemm_core(g_Ah, g_Al, g_w_hi[3], g_w_lo[3], m0, n0, tb, acc);

    int tid = threadIdx.x;
    int wid = tid >> 5;
    int lane = tid & 31;
    int wm = (wid >> 2) * 64;
    int wn = (wid & 3) * 64;
    int group = lane >> 2, tig = lane & 3;
#pragma unroll
    for (int i = 0; i < 4; i++) {
#pragma unroll
        for (int jn = 0; jn < 8; jn++) {
            int row = m0 + wm + i * 16 + group;
            int col = n0 + wn + jn * 8 + tig * 2;
            float2 v0 = make_float2(acc[i][jn][0], acc[i][jn][1]);
            float2 v1 = make_float2(acc[i][jn][2], acc[i][jn][3]);
            *(float2*)(C + (size_t)row * HDIM + col) = v0;
            *(float2*)(C + (size_t)(row + 8) * HDIM + col) = v1;
        }
    }
}

// ---------------------------------------------------------------------------
// Tensor-core flash attention (unchanged from R12/R15).
// Grid (S/128, BATCH*NHEAD) = (16, 64); 256 threads (8 warps x 16 q rows).
// ---------------------------------------------------------------------------
#define AROWB 144
#define QTILEB (128 * AROWB)            // 18432
#define KVTILEB (64 * AROWB)            // 9216
#define KVSTAGEB (4 * KVTILEB)          // 36864
#define ATT_SMEM (2 * QTILEB + 2 * KVSTAGEB)   // 110592

__global__ void __launch_bounds__(256, 2)
flash_tc_kernel()
{
    extern __shared__ char smem[];
    uint32_t sb  = smem_u32(smem);
    uint32_t sQh = sb;
    uint32_t sQl = sb + QTILEB;
    uint32_t sKV = sb + 2 * QTILEB;

    int tid = threadIdx.x;
    int wid = tid >> 5;
    int lane = tid & 31;
    int group = lane >> 2, tig = lane & 3;
    int bh = blockIdx.y;
    int b  = bh >> 4;
    int h  = bh & 15;
    int q0 = blockIdx.x * 128;
    int len = g_len[b];

    // ---- Q tile load (group A) ----
    {
        const char* gq[2] = { (const char*)g_Qh, (const char*)g_Ql };
#pragma unroll
        for (int j = 0; j < 8; j++) {
            int idx = tid + j * 256;
            int t = idx >> 10;
            int r = (idx >> 3) & 127;
            int p = idx & 7;
            cp16((t ? sQl : sQh) + r * AROWB + p * 16,
                 gq[t] + ((size_t)((q0 + r) * BATCH + b) * HDIM + h * DKDIM) * 2 + p * 16);
        }
    }
    asm volatile("cp.async.commit_group;");

    const char* gkv[4] = { (const char*)g_Kh, (const char*)g_Kl,
                           (const char*)g_Vh, (const char*)g_Vl };
    auto load_kv = [&](int stage, int k0) {
        uint32_t sbase = sKV + stage * KVSTAGEB;
#pragma unroll
        for (int j = 0; j < 8; j++) {
            int idx = tid + j * 256;
            int t = idx >> 9;
            int r = (idx >> 3) & 63;
            int p = idx & 7;
            cp16(sbase + t * KVTILEB + r * AROWB + p * 16,
                 gkv[t] + ((size_t)((k0 + r) * BATCH + b) * HDIM + h * DKDIM) * 2 + p * 16);
        }
    };

    load_kv(0, 0);
    asm volatile("cp.async.commit_group;");
    asm volatile("cp.async.wait_group 1;" ::: "memory");
    __syncthreads();

    // persistent Q-hi fragments only (Q-lo reloaded per k-tile from smem)
    uint32_t qah[4][4];
#pragma unroll
    for (int kt = 0; kt < 4; kt++) {
        uint32_t ra = sQh + (uint32_t)(wid * 16 + (lane & 15)) * AROWB
                    + kt * 32 + (lane >> 4) * 16;
        ldsm4(qah[kt], ra);
    }

    float mi0 = -INFINITY, mi1 = -INFINITY;
    float li0 = 0.0f, li1 = 0.0f;
    float oacc[8][4];
#pragma unroll
    for (int j = 0; j < 8; j++)
#pragma unroll
        for (int r = 0; r < 4; r++) oacc[j][r] = 0.0f;

    int nkt = (len + 63) >> 6;
    for (int it = 0; it < nkt; it++) {
        if (it + 1 < nkt) {
            load_kv((it + 1) & 1, (it + 1) * 64);
            asm volatile("cp.async.commit_group;");
            asm volatile("cp.async.wait_group 1;" ::: "memory");
        } else {
            asm volatile("cp.async.wait_group 0;" ::: "memory");
        }
        __syncthreads();

        uint32_t kb = sKV + (it & 1) * KVSTAGEB;
        uint32_t vb = kb + 2 * KVTILEB;
        int k0 = it * 64;

        float sacc[8][4];
#pragma unroll
        for (int j = 0; j < 8; j++)
#pragma unroll
            for (int r = 0; r < 4; r++) sacc[j][r] = 0.0f;

#pragma unroll
        for (int kt = 0; kt < 4; kt++) {
            uint32_t qalf[4];
            ldsm4(qalf, sQl + (uint32_t)(wid * 16 + (lane & 15)) * AROWB
                        + kt * 32 + (lane >> 4) * 16);
#pragma unroll
            for (int j2 = 0; j2 < 4; j2++) {
                uint32_t bhf[4], blf[4];
                uint32_t rb = kb + (uint32_t)(j2 * 16 + (lane & 15)) * AROWB
                            + kt * 32 + (lane >> 4) * 16;
                ldsm4(bhf, rb);
                ldsm4(blf, rb + KVTILEB);
                mma16816(sacc[j2 * 2],     qah[kt], bhf[0], bhf[2]);
                mma16816(sacc[j2 * 2],     qah[kt], blf[0], blf[2]);
                mma16816(sacc[j2 * 2],     qalf,    bhf[0], bhf[2]);
                mma16816(sacc[j2 * 2 + 1], qah[kt], bhf[1], bhf[3]);
                mma16816(sacc[j2 * 2 + 1], qah[kt], blf[1], blf[3]);
                mma16816(sacc[j2 * 2 + 1], qalf,    bhf[1], bhf[3]);
            }
        }

        if (k0 + 64 > len) {
#pragma unroll
            for (int j = 0; j < 8; j++) {
                int col = k0 + j * 8 + tig * 2;
                if (col >= len)     { sacc[j][0] = -INFINITY; sacc[j][2] = -INFINITY; }
                if (col + 1 >= len) { sacc[j][1] = -INFINITY; sacc[j][3] = -INFINITY; }
            }
        }

        float m0 = -INFINITY, m1 = -INFINITY;
#pragma unroll
        for (int j = 0; j < 8; j++) {
            m0 = fmaxf(m0, fmaxf(sacc[j][0], sacc[j][1]));
            m1 = fmaxf(m1, fmaxf(sacc[j][2], sacc[j][3]));
        }
        m0 = fmaxf(m0, __shfl_xor_sync(0xffffffffu, m0, 1));
        m0 = fmaxf(m0, __shfl_xor_sync(0xffffffffu, m0, 2));
        m1 = fmaxf(m1, __shfl_xor_sync(0xffffffffu, m1, 1));
        m1 = fmaxf(m1, __shfl_xor_sync(0xffffffffu, m1, 2));

        float mn0 = fmaxf(mi0, m0);
        float mn1 = fmaxf(mi1, m1);
        float sc0 = __expf(mi0 - mn0);
        float sc1 = __expf(mi1 - mn1);
        mi0 = mn0;
        mi1 = mn1;

        float sum0 = 0.0f, sum1 = 0.0f;
#pragma unroll
        for (int j = 0; j < 8; j++) {
            sacc[j][0] = __expf(sacc[j][0] - mn0);
            sacc[j][1] = __expf(sacc[j][1] - mn0);
            sacc[j][2] = __expf(sacc[j][2] - mn1);
            sacc[j][3] = __expf(sacc[j][3] - mn1);
            sum0 += sacc[j][0] + sacc[j][1];
            sum1 += sacc[j][2] + sacc[j][3];
        }
        sum0 += __shfl_xor_sync(0xffffffffu, sum0, 1);
        sum0 += __shfl_xor_sync(0xffffffffu, sum0, 2);
        sum1 += __shfl_xor_sync(0xffffffffu, sum1, 1);
        sum1 += __shfl_xor_sync(0xffffffffu, sum1, 2);
        li0 = li0 * sc0 + sum0;
        li1 = li1 * sc1 + sum1;

#pragma unroll
        for (int j = 0; j < 8; j++) {
            oacc[j][0] *= sc0;
            oacc[j][1] *= sc0;
            oacc[j][2] *= sc1;
            oacc[j][3] *= sc1;
        }

#pragma unroll
        for (int kt = 0; kt < 4; kt++) {
            uint32_t phi[4], plo[4];
            split2(sacc[2 * kt][0],     sacc[2 * kt][1],     phi[0], plo[0]);
            split2(sacc[2 * kt][2],     sacc[2 * kt][3],     phi[1], plo[1]);
            split2(sacc[2 * kt + 1][0], sacc[2 * kt + 1][1], phi[2], plo[2]);
            split2(sacc[2 * kt + 1][2], sacc[2 * kt + 1][3], phi[3], plo[3]);

#pragma unroll
            for (int n2 = 0; n2 < 4; n2++) {
                uint32_t vhf[4], vlf[4];
                uint32_t va = vb + (uint32_t)(kt * 16 + ((lane >> 3) & 1) * 8 + (lane & 7)) * AROWB
                            + n2 * 32 + (lane >> 4) * 16;
                ldsm4t(vhf, va);
                ldsm4t(vlf, va + KVTILEB);
                mma16816(oacc[n2 * 2],     phi, vhf[0], vhf[1]);
                mma16816(oacc[n2 * 2],     phi, vlf[0], vlf[1]);
                mma16816(oacc[n2 * 2],     plo, vhf[0], vhf[1]);
                mma16816(oacc[n2 * 2 + 1], phi, vhf[2], vhf[3]);
                mma16816(oacc[n2 * 2 + 1], phi, vlf[2], vlf[3]);
                mma16816(oacc[n2 * 2 + 1], plo, vhf[2], vhf[3]);
            }
        }
        __syncthreads();
    }

    // ---- epilogue: normalize; PAD query rows -> 0; write bf16 hi/lo ----
    int row0 = q0 + wid * 16 + group;
    int row1 = row0 + 8;
    float inv0 = (row0 < len) ? (1.0f / li0) : 0.0f;
    float inv1 = (row1 < len) ? (1.0f / li1) : 0.0f;
#pragma unroll
    for (int j = 0; j < 8; j++) {
        int col = h * DKDIM + j * 8 + tig * 2;
        uint32_t h0, l0, h1, l1;
        split2(oacc[j][0] * inv0, oacc[j][1] * inv0, h0, l0);
        split2(oacc[j][2] * inv1, oacc[j][3] * inv1, h1, l1);
        size_t o0 = (size_t)(row0 * BATCH + b) * HDIM + col;
        size_t o1 = (size_t)(row1 * BATCH + b) * HDIM + col;
        *(uint32_t*)(g_Ah + o0) = h0;
        *(uint32_t*)(g_Al + o0) = l0;
        *(uint32_t*)(g_Ah + o1) = h1;
        *(uint32_t*)(g_Al + o1) = l1;
    }
}

// ---------------------------------------------------------------------------
// Launch
// ---------------------------------------------------------------------------
extern "C" void kernel_launch(void* const* d_in, const int* in_sizes, int n_in,
                              void* d_out, int out_size)
{
    const float* value = (const float*)d_in[0];
    const float* key   = (const float*)d_in[1];
    const float* query = (const float*)d_in[2];
    const float* Wq = (const float*)d_in[4];
    const float* Wk = (const float*)d_in[5];
    const float* Wv = (const float*)d_in[6];
    const float* Wo = (const float*)d_in[7];
    float* out = (float*)d_out;

    static bool attr_set = false;
    if (!attr_set) {
        cudaFuncSetAttribute(qkv_gemm_kernel,
                             cudaFuncAttributeMaxDynamicSharedMemorySize, GEMM_SMEM_BYTES);
        cudaFuncSetAttribute(wo_gemm_kernel,
                             cudaFuncAttributeMaxDynamicSharedMemorySize, GEMM_SMEM_BYTES);
        cudaFuncSetAttribute(flash_tc_kernel,
                             cudaFuncAttributeMaxDynamicSharedMemorySize, ATT_SMEM);
        attr_set = true;
    }

    // lengths from raw key rows (PAD rows are exactly zero)
    len_kernel<<<BATCH, 512>>>(key);

    // input + weight hi/lo splits (fused launches)
    dim3 inGrid((MROWS * HDIM) / (256 * 4), 3);    // (8192, 3)
    dim3 wGrid((HDIM * HDIM) / (256 * 4), 4);      // (1024, 4)
    convert_in_kernel<<<inGrid, 256>>>(query, key, value);
    convert_w_kernel<<<wGrid, 256>>>(Wq, Wk, Wv, Wo);

    // QKV projections, fused in one launch (split bf16 epilogue)
    dim3 qkvGrid(HDIM / 256, MROWS / 128, 3);      // (4, 64, 3)
    qkv_gemm_kernel<<<qkvGrid, 256, GEMM_SMEM_BYTES>>>();

    // attention (tensor cores), writes A split directly
    dim3 flashGrid(S_LEN / 128, BATCH * NHEAD);    // (16, 64)
    flash_tc_kernel<<<flashGrid, 256, ATT_SMEM>>>();

    // output projection
    dim3 gemmGrid(HDIM / 256, MROWS / 128);        // (4, 64)
    wo_gemm_kernel<<<gemmGrid, 256, GEMM_SMEM_BYTES>>>(out);
}

// round 17
// speedup vs baseline: 1.0966x; 1.0966x over previous
#include <cuda_runtime.h>
#include <cuda_bf16.h>
#include <math.h>
#include <stdint.h>

// Problem constants
#define S_LEN 2048
#define BATCH 4
#define HDIM  1024
#define NHEAD 16
#define DKDIM 64
#define MROWS (S_LEN * BATCH)   // 8192

// ---------------------------------------------------------------------------
// Scratch (static device globals)
// ---------------------------------------------------------------------------
__device__ __nv_bfloat16 g_in_hi[3][(size_t)MROWS * HDIM];  // split(query/key/value)
__device__ __nv_bfloat16 g_in_lo[3][(size_t)MROWS * HDIM];
__device__ __nv_bfloat16 g_w_hi[4][(size_t)HDIM * HDIM];    // split(Wq/Wk/Wv/Wo)
__device__ __nv_bfloat16 g_w_lo[4][(size_t)HDIM * HDIM];
__device__ __nv_bfloat16 g_Qh[(size_t)MROWS * HDIM];        // projected, split
__device__ __nv_bfloat16 g_Ql[(size_t)MROWS * HDIM];
__device__ __nv_bfloat16 g_Kh[(size_t)MROWS * HDIM];
__device__ __nv_bfloat16 g_Kl[(size_t)MROWS * HDIM];
__device__ __nv_bfloat16 g_Vh[(size_t)MROWS * HDIM];
__device__ __nv_bfloat16 g_Vl[(size_t)MROWS * HDIM];
__device__ __nv_bfloat16 g_Ah[(size_t)MROWS * HDIM];        // attention out, split
__device__ __nv_bfloat16 g_Al[(size_t)MROWS * HDIM];
__device__ int g_len[BATCH];

// ---------------------------------------------------------------------------
// PTX helpers (non-'a' features only: ldmatrix / mma.sync / cp.async)
// ---------------------------------------------------------------------------
__device__ __forceinline__ uint32_t smem_u32(const void* p) {
    uint32_t a;
    asm("{ .reg .u64 t; cvta.to.shared.u64 t, %1; cvt.u32.u64 %0, t; }"
        : "=r"(a) : "l"(p));
    return a;
}

__device__ __forceinline__ void cp16(uint32_t s, const void* g) {
    asm volatile("cp.async.cg.shared.global [%0], [%1], 16;" :: "r"(s), "l"(g));
}

__device__ __forceinline__ void ldsm4(uint32_t* r, uint32_t addr) {
    asm volatile("ldmatrix.sync.aligned.m8n8.x4.shared.b16 {%0,%1,%2,%3}, [%4];"
                 : "=r"(r[0]), "=r"(r[1]), "=r"(r[2]), "=r"(r[3]) : "r"(addr));
}

__device__ __forceinline__ void ldsm4t(uint32_t* r, uint32_t addr) {
    asm volatile("ldmatrix.sync.aligned.m8n8.x4.trans.shared.b16 {%0,%1,%2,%3}, [%4];"
                 : "=r"(r[0]), "=r"(r[1]), "=r"(r[2]), "=r"(r[3]) : "r"(addr));
}

__device__ __forceinline__ void mma16816(float* d, const uint32_t* a,
                                         uint32_t b0, uint32_t b1) {
    asm volatile(
        "mma.sync.aligned.m16n8k16.row.col.f32.bf16.bf16.f32 "
        "{%0,%1,%2,%3}, {%4,%5,%6,%7}, {%8,%9}, {%0,%1,%2,%3};"
        : "+f"(d[0]), "+f"(d[1]), "+f"(d[2]), "+f"(d[3])
        : "r"(a[0]), "r"(a[1]), "r"(a[2]), "r"(a[3]), "r"(b0), "r"(b1));
}

// split pair of floats into bf16x2 hi + lo words
__device__ __forceinline__ void split2(float a, float b, uint32_t& hi, uint32_t& lo) {
    __nv_bfloat16 ha = __float2bfloat16(a);
    __nv_bfloat16 hb = __float2bfloat16(b);
    float ra = a - __bfloat162float(ha);
    float rb = b - __bfloat162float(hb);
    __nv_bfloat162 th = __halves2bfloat162(ha, hb);
    __nv_bfloat162 tl = __halves2bfloat162(__float2bfloat16(ra), __float2bfloat16(rb));
    hi = *(uint32_t*)&th;
    lo = *(uint32_t*)&tl;
}

// ---------------------------------------------------------------------------
// Per-batch valid length
// ---------------------------------------------------------------------------
__global__ void __launch_bounds__(512)
len_kernel(const float* __restrict__ key)
{
    __shared__ int sh[512];
    int b = blockIdx.x;
    int cnt = 0;
    for (int s = threadIdx.x; s < S_LEN; s += 512) {
        float4 v = *(const float4*)(key + (size_t)(s * BATCH + b) * HDIM);
        cnt += (v.x != 0.0f || v.y != 0.0f || v.z != 0.0f || v.w != 0.0f) ? 1 : 0;
    }
    sh[threadIdx.x] = cnt;
    __syncthreads();
    for (int o = 256; o > 0; o >>= 1) {
        if (threadIdx.x < o) sh[threadIdx.x] += sh[threadIdx.x + o];
        __syncthreads();
    }
    if (threadIdx.x == 0) g_len[b] = sh[0];
}

// ---------------------------------------------------------------------------
// fp32 -> bf16 hi/lo splits (fused multi-tensor launches)
// ---------------------------------------------------------------------------
__device__ __forceinline__ void split_store(const float* src, __nv_bfloat16* hi,
                                            __nv_bfloat16* lo, size_t i)
{
    float4 v = *(const float4*)(src + i);
    uint32_t h0, l0, h1, l1;
    split2(v.x, v.y, h0, l0);
    split2(v.z, v.w, h1, l1);
    uint32_t* hp = (uint32_t*)(hi + i);
    uint32_t* lp = (uint32_t*)(lo + i);
    hp[0] = h0; hp[1] = h1;
    lp[0] = l0; lp[1] = l1;
}

__global__ void __launch_bounds__(256)
convert_in_kernel(const float* __restrict__ q, const float* __restrict__ k,
                  const float* __restrict__ v)
{
    int t = blockIdx.y;
    const float* src = (t == 0) ? q : (t == 1) ? k : v;
    size_t i = ((size_t)blockIdx.x * 256 + threadIdx.x) * 4;
    split_store(src, g_in_hi[t], g_in_lo[t], i);
}

__global__ void __launch_bounds__(256)
convert_w_kernel(const float* __restrict__ wq, const float* __restrict__ wk,
                 const float* __restrict__ wv, const float* __restrict__ wo)
{
    int t = blockIdx.y;
    const float* src = (t == 0) ? wq : (t == 1) ? wk : (t == 2) ? wv : wo;
    size_t i = ((size_t)blockIdx.x * 256 + threadIdx.x) * 4;
    split_store(src, g_w_hi[t], g_w_lo[t], i);
}

// ---------------------------------------------------------------------------
// HMMA GEMM core (NT): acc = sum_k A[m][k] * W[n][k], bf16 hi/lo split
// (D += Ah*Wh + Ah*Wl + Al*Wh).
// CTA tile 128x128, 4 warps (2x2), warp tile 64x64 — cutlass sm80 shape:
// 128 threads, ~245 regs -> 2 CTAs/SM (independent CTAs cover barrier stalls).
// XOR-swizzled SMEM, 3-stage cp.async pipeline, 1 sync/chunk.
// ---------------------------------------------------------------------------
#define TILEB 8192                      // 128 rows x 64B
#define STAGEB (4 * TILEB)              // 32768: Ah, Al, Bh, Bl
#define GEMM_SMEM_BYTES (3 * STAGEB)    // 98304; 2 CTAs = 192KB <= 227KB

// swizzled byte offset of 16B piece p (0..3) in row r (64B rows)
__device__ __forceinline__ uint32_t gswz(uint32_t r, uint32_t p) {
    return r * 64 + ((p ^ ((r >> 1) & 3)) << 4);
}

__device__ __forceinline__ void gemm_core(
    const __nv_bfloat16* Ahi, const __nv_bfloat16* Alo,
    const __nv_bfloat16* Bhi, const __nv_bfloat16* Blo,
    int m0, int n0, uint32_t tb, float acc[4][8][4])
{
    int tid = threadIdx.x;              // 0..127
    int wid = tid >> 5;                 // 0..3
    int lane = tid & 31;
    int wm = (wid >> 1) * 64;           // 2 warp rows
    int wn = (wid & 1) * 64;            // 2 warp cols

    const char* gsrc[4];
    gsrc[0] = (const char*)(Ahi + (size_t)m0 * HDIM);
    gsrc[1] = (const char*)(Alo + (size_t)m0 * HDIM);
    gsrc[2] = (const char*)(Bhi + (size_t)n0 * HDIM);
    gsrc[3] = (const char*)(Blo + (size_t)n0 * HDIM);

#pragma unroll
    for (int i = 0; i < 4; i++)
#pragma unroll
        for (int j = 0; j < 8; j++)
#pragma unroll
            for (int r = 0; r < 4; r++) acc[i][j][r] = 0.0f;

    const int NC = HDIM / 32;           // 32 chunks

    auto load_stage = [&](int stage, int c) {
        uint32_t sbase = tb + stage * STAGEB;
        int kbyte = c * 64;
#pragma unroll
        for (int j = 0; j < 16; j++) {
            int idx = tid + j * 128;    // 0..2047
            int t = idx >> 9;           // tile 0..3
            uint32_t r = (idx >> 2) & 127;
            uint32_t p = idx & 3;
            cp16(sbase + t * TILEB + gswz(r, p),
                 gsrc[t] + (size_t)r * 2048 + kbyte + p * 16);
        }
        asm volatile("cp.async.commit_group;");
    };

    load_stage(0, 0);
    load_stage(1, 1);

    int stage = 0, nstage = 2;
    for (int c = 0; c < NC; c++) {
        if (c < NC - 1) {
            asm volatile("cp.async.wait_group 1;" ::: "memory");
        } else {
            asm volatile("cp.async.wait_group 0;" ::: "memory");
        }
        __syncthreads();                 // stage c visible; oldest stage free
        if (c + 2 < NC)
            load_stage(nstage, c + 2);

        uint32_t abase = tb + stage * STAGEB;
        uint32_t bbase = abase + 2 * TILEB;
#pragma unroll
        for (int kh = 0; kh < 2; kh++) {
            uint32_t p = (uint32_t)(kh * 2 + (lane >> 4));
            uint32_t bh[4][4], bl[4][4];
#pragma unroll
            for (int j = 0; j < 4; j++) {
                uint32_t r = (uint32_t)(wn + j * 16 + (lane & 15));
                uint32_t off = gswz(r, p);
                ldsm4(bh[j], bbase + off);
                ldsm4(bl[j], bbase + TILEB + off);
            }
#pragma unroll
            for (int i = 0; i < 4; i++) {
                uint32_t r = (uint32_t)(wm + i * 16 + (lane & 15));
                uint32_t off = gswz(r, p);
                uint32_t ah[4], al[4];
                ldsm4(ah, abase + off);
                ldsm4(al, abase + TILEB + off);
#pragma unroll
                for (int jn = 0; jn < 8; jn++) {
                    int j = jn >> 1, h = jn & 1;
                    mma16816(acc[i][jn], ah, bh[j][h], bh[j][h + 2]);
                    mma16816(acc[i][jn], ah, bl[j][h], bl[j][h + 2]);
                    mma16816(acc[i][jn], al, bh[j][h], bh[j][h + 2]);
                }
            }
        }
        stage = (stage == 2) ? 0 : stage + 1;
        nstage = (nstage == 2) ? 0 : nstage + 1;
    }
}

// ---- QKV projections fused (grid z = 0/1/2), split bf16 output ----
__global__ void __launch_bounds__(128, 2)
qkv_gemm_kernel()
{
    extern __shared__ char smem[];
    uint32_t tb = smem_u32(smem);
    int z = blockIdx.z;
    int m0 = blockIdx.y * 128;
    int n0 = blockIdx.x * 128;
    float alpha = (z == 0) ? 0.125f : 1.0f;   // 1/sqrt(DK) folded into Q

    float acc[4][8][4];
    gemm_core(g_in_hi[z], g_in_lo[z], g_w_hi[z], g_w_lo[z], m0, n0, tb, acc);

    __nv_bfloat16* Ohi = (z == 0) ? g_Qh : (z == 1) ? g_Kh : g_Vh;
    __nv_bfloat16* Olo = (z == 0) ? g_Ql : (z == 1) ? g_Kl : g_Vl;

    int tid = threadIdx.x;
    int wid = tid >> 5;
    int lane = tid & 31;
    int wm = (wid >> 1) * 64;
    int wn = (wid & 1) * 64;
    int group = lane >> 2, tig = lane & 3;
#pragma unroll
    for (int i = 0; i < 4; i++) {
#pragma unroll
        for (int jn = 0; jn < 8; jn++) {
            int row = m0 + wm + i * 16 + group;
            int col = n0 + wn + jn * 8 + tig * 2;
            uint32_t h0, l0, h1, l1;
            split2(alpha * acc[i][jn][0], alpha * acc[i][jn][1], h0, l0);
            split2(alpha * acc[i][jn][2], alpha * acc[i][jn][3], h1, l1);
            size_t o0 = (size_t)row * HDIM + col;
            size_t o1 = (size_t)(row + 8) * HDIM + col;
            *(uint32_t*)(Ohi + o0) = h0;
            *(uint32_t*)(Olo + o0) = l0;
            *(uint32_t*)(Ohi + o1) = h1;
            *(uint32_t*)(Olo + o1) = l1;
        }
    }
}

// ---- output projection: A = attention (g_Ah/g_Al), W = Wo, fp32 out ----
__global__ void __launch_bounds__(128, 2)
wo_gemm_kernel(float* __restrict__ C)
{
    extern __shared__ char smem[];
    uint32_t tb = smem_u32(smem);
    int m0 = blockIdx.y * 128;
    int n0 = blockIdx.x * 128;

    float acc[4][8][4];
    gemm_core(g_Ah, g_Al, g_w_hi[3], g_w_lo[3], m0, n0, tb, acc);

    int tid = threadIdx.x;
    int wid = tid >> 5;
    int lane = tid & 31;
    int wm = (wid >> 1) * 64;
    int wn = (wid & 1) * 64;
    int group = lane >> 2, tig = lane & 3;
#pragma unroll
    for (int i = 0; i < 4; i++) {
#pragma unroll
        for (int jn = 0; jn < 8; jn++) {
            int row = m0 + wm + i * 16 + group;
            int col = n0 + wn + jn * 8 + tig * 2;
            float2 v0 = make_float2(acc[i][jn][0], acc[i][jn][1]);
            float2 v1 = make_float2(acc[i][jn][2], acc[i][jn][3]);
            *(float2*)(C + (size_t)row * HDIM + col) = v0;
            *(float2*)(C + (size_t)(row + 8) * HDIM + col) = v1;
        }
    }
}

// ---------------------------------------------------------------------------
// Tensor-core flash attention (unchanged).
// Grid (S/128, BATCH*NHEAD) = (16, 64); 256 threads (8 warps x 16 q rows).
// ---------------------------------------------------------------------------
#define AROWB 144
#define QTILEB (128 * AROWB)            // 18432
#define KVTILEB (64 * AROWB)            // 9216
#define KVSTAGEB (4 * KVTILEB)          // 36864
#define ATT_SMEM (2 * QTILEB + 2 * KVSTAGEB)   // 110592

__global__ void __launch_bounds__(256, 2)
flash_tc_kernel()
{
    extern __shared__ char smem[];
    uint32_t sb  = smem_u32(smem);
    uint32_t sQh = sb;
    uint32_t sQl = sb + QTILEB;
    uint32_t sKV = sb + 2 * QTILEB;

    int tid = threadIdx.x;
    int wid = tid >> 5;
    int lane = tid & 31;
    int group = lane >> 2, tig = lane & 3;
    int bh = blockIdx.y;
    int b  = bh >> 4;
    int h  = bh & 15;
    int q0 = blockIdx.x * 128;
    int len = g_len[b];

    // ---- Q tile load (group A) ----
    {
        const char* gq[2] = { (const char*)g_Qh, (const char*)g_Ql };
#pragma unroll
        for (int j = 0; j < 8; j++) {
            int idx = tid + j * 256;
            int t = idx >> 10;
            int r = (idx >> 3) & 127;
            int p = idx & 7;
            cp16((t ? sQl : sQh) + r * AROWB + p * 16,
                 gq[t] + ((size_t)((q0 + r) * BATCH + b) * HDIM + h * DKDIM) * 2 + p * 16);
        }
    }
    asm volatile("cp.async.commit_group;");

    const char* gkv[4] = { (const char*)g_Kh, (const char*)g_Kl,
                           (const char*)g_Vh, (const char*)g_Vl };
    auto load_kv = [&](int stage, int k0) {
        uint32_t sbase = sKV + stage * KVSTAGEB;
#pragma unroll
        for (int j = 0; j < 8; j++) {
            int idx = tid + j * 256;
            int t = idx >> 9;
            int r = (idx >> 3) & 63;
            int p = idx & 7;
            cp16(sbase + t * KVTILEB + r * AROWB + p * 16,
                 gkv[t] + ((size_t)((k0 + r) * BATCH + b) * HDIM + h * DKDIM) * 2 + p * 16);
        }
    };

    load_kv(0, 0);
    asm volatile("cp.async.commit_group;");
    asm volatile("cp.async.wait_group 1;" ::: "memory");
    __syncthreads();

    // persistent Q-hi fragments only (Q-lo reloaded per k-tile from smem)
    uint32_t qah[4][4];
#pragma unroll
    for (int kt = 0; kt < 4; kt++) {
        uint32_t ra = sQh + (uint32_t)(wid * 16 + (lane & 15)) * AROWB
                    + kt * 32 + (lane >> 4) * 16;
        ldsm4(qah[kt], ra);
    }

    float mi0 = -INFINITY, mi1 = -INFINITY;
    float li0 = 0.0f, li1 = 0.0f;
    float oacc[8][4];
#pragma unroll
    for (int j = 0; j < 8; j++)
#pragma unroll
        for (int r = 0; r < 4; r++) oacc[j][r] = 0.0f;

    int nkt = (len + 63) >> 6;
    for (int it = 0; it < nkt; it++) {
        if (it + 1 < nkt) {
            load_kv((it + 1) & 1, (it + 1) * 64);
            asm volatile("cp.async.commit_group;");
            asm volatile("cp.async.wait_group 1;" ::: "memory");
        } else {
            asm volatile("cp.async.wait_group 0;" ::: "memory");
        }
        __syncthreads();

        uint32_t kb = sKV + (it & 1) * KVSTAGEB;
        uint32_t vb = kb + 2 * KVTILEB;
        int k0 = it * 64;

        float sacc[8][4];
#pragma unroll
        for (int j = 0; j < 8; j++)
#pragma unroll
            for (int r = 0; r < 4; r++) sacc[j][r] = 0.0f;

#pragma unroll
        for (int kt = 0; kt < 4; kt++) {
            uint32_t qalf[4];
            ldsm4(qalf, sQl + (uint32_t)(wid * 16 + (lane & 15)) * AROWB
                        + kt * 32 + (lane >> 4) * 16);
#pragma unroll
            for (int j2 = 0; j2 < 4; j2++) {
                uint32_t bhf[4], blf[4];
                uint32_t rb = kb + (uint32_t)(j2 * 16 + (lane & 15)) * AROWB
                            + kt * 32 + (lane >> 4) * 16;
                ldsm4(bhf, rb);
                ldsm4(blf, rb + KVTILEB);
                mma16816(sacc[j2 * 2],     qah[kt], bhf[0], bhf[2]);
                mma16816(sacc[j2 * 2],     qah[kt], blf[0], blf[2]);
                mma16816(sacc[j2 * 2],     qalf,    bhf[0], bhf[2]);
                mma16816(sacc[j2 * 2 + 1], qah[kt], bhf[1], bhf[3]);
                mma16816(sacc[j2 * 2 + 1], qah[kt], blf[1], blf[3]);
                mma16816(sacc[j2 * 2 + 1], qalf,    bhf[1], bhf[3]);
            }
        }

        if (k0 + 64 > len) {
#pragma unroll
            for (int j = 0; j < 8; j++) {
                int col = k0 + j * 8 + tig * 2;
                if (col >= len)     { sacc[j][0] = -INFINITY; sacc[j][2] = -INFINITY; }
                if (col + 1 >= len) { sacc[j][1] = -INFINITY; sacc[j][3] = -INFINITY; }
            }
        }

        float m0 = -INFINITY, m1 = -INFINITY;
#pragma unroll
        for (int j = 0; j < 8; j++) {
            m0 = fmaxf(m0, fmaxf(sacc[j][0], sacc[j][1]));
            m1 = fmaxf(m1, fmaxf(sacc[j][2], sacc[j][3]));
        }
        m0 = fmaxf(m0, __shfl_xor_sync(0xffffffffu, m0, 1));
        m0 = fmaxf(m0, __shfl_xor_sync(0xffffffffu, m0, 2));
        m1 = fmaxf(m1, __shfl_xor_sync(0xffffffffu, m1, 1));
        m1 = fmaxf(m1, __shfl_xor_sync(0xffffffffu, m1, 2));

        float mn0 = fmaxf(mi0, m0);
        float mn1 = fmaxf(mi1, m1);
        float sc0 = __expf(mi0 - mn0);
        float sc1 = __expf(mi1 - mn1);
        mi0 = mn0;
        mi1 = mn1;

        float sum0 = 0.0f, sum1 = 0.0f;
#pragma unroll
        for (int j = 0; j < 8; j++) {
            sacc[j][0] = __expf(sacc[j][0] - mn0);
            sacc[j][1] = __expf(sacc[j][1] - mn0);
            sacc[j][2] = __expf(sacc[j][2] - mn1);
            sacc[j][3] = __expf(sacc[j][3] - mn1);
            sum0 += sacc[j][0] + sacc[j][1];
            sum1 += sacc[j][2] + sacc[j][3];
        }
        sum0 += __shfl_xor_sync(0xffffffffu, sum0, 1);
        sum0 += __shfl_xor_sync(0xffffffffu, sum0, 2);
        sum1 += __shfl_xor_sync(0xffffffffu, sum1, 1);
        sum1 += __shfl_xor_sync(0xffffffffu, sum1, 2);
        li0 = li0 * sc0 + sum0;
        li1 = li1 * sc1 + sum1;

#pragma unroll
        for (int j = 0; j < 8; j++) {
            oacc[j][0] *= sc0;
            oacc[j][1] *= sc0;
            oacc[j][2] *= sc1;
            oacc[j][3] *= sc1;
        }

#pragma unroll
        for (int kt = 0; kt < 4; kt++) {
            uint32_t phi[4], plo[4];
            split2(sacc[2 * kt][0],     sacc[2 * kt][1],     phi[0], plo[0]);
            split2(sacc[2 * kt][2],     sacc[2 * kt][3],     phi[1], plo[1]);
            split2(sacc[2 * kt + 1][0], sacc[2 * kt + 1][1], phi[2], plo[2]);
            split2(sacc[2 * kt + 1][2], sacc[2 * kt + 1][3], phi[3], plo[3]);

#pragma unroll
            for (int n2 = 0; n2 < 4; n2++) {
                uint32_t vhf[4], vlf[4];
                uint32_t va = vb + (uint32_t)(kt * 16 + ((lane >> 3) & 1) * 8 + (lane & 7)) * AROWB
                            + n2 * 32 + (lane >> 4) * 16;
                ldsm4t(vhf, va);
                ldsm4t(vlf, va + KVTILEB);
                mma16816(oacc[n2 * 2],     phi, vhf[0], vhf[1]);
                mma16816(oacc[n2 * 2],     phi, vlf[0], vlf[1]);
                mma16816(oacc[n2 * 2],     plo, vhf[0], vhf[1]);
                mma16816(oacc[n2 * 2 + 1], phi, vhf[2], vhf[3]);
                mma16816(oacc[n2 * 2 + 1], phi, vlf[2], vlf[3]);
                mma16816(oacc[n2 * 2 + 1], plo, vhf[2], vhf[3]);
            }
        }
        __syncthreads();
    }

    // ---- epilogue: normalize; PAD query rows -> 0; write bf16 hi/lo ----
    int row0 = q0 + wid * 16 + group;
    int row1 = row0 + 8;
    float inv0 = (row0 < len) ? (1.0f / li0) : 0.0f;
    float inv1 = (row1 < len) ? (1.0f / li1) : 0.0f;
#pragma unroll
    for (int j = 0; j < 8; j++) {
        int col = h * DKDIM + j * 8 + tig * 2;
        uint32_t h0, l0, h1, l1;
        split2(oacc[j][0] * inv0, oacc[j][1] * inv0, h0, l0);
        split2(oacc[j][2] * inv1, oacc[j][3] * inv1, h1, l1);
        size_t o0 = (size_t)(row0 * BATCH + b) * HDIM + col;
        size_t o1 = (size_t)(row1 * BATCH + b) * HDIM + col;
        *(uint32_t*)(g_Ah + o0) = h0;
        *(uint32_t*)(g_Al + o0) = l0;
        *(uint32_t*)(g_Ah + o1) = h1;
        *(uint32_t*)(g_Al + o1) = l1;
    }
}

// ---------------------------------------------------------------------------
// Launch
// ---------------------------------------------------------------------------
extern "C" void kernel_launch(void* const* d_in, const int* in_sizes, int n_in,
                              void* d_out, int out_size)
{
    const float* value = (const float*)d_in[0];
    const float* key   = (const float*)d_in[1];
    const float* query = (const float*)d_in[2];
    const float* Wq = (const float*)d_in[4];
    const float* Wk = (const float*)d_in[5];
    const float* Wv = (const float*)d_in[6];
    const float* Wo = (const float*)d_in[7];
    float* out = (float*)d_out;

    static bool attr_set = false;
    if (!attr_set) {
        cudaFuncSetAttribute(qkv_gemm_kernel,
                             cudaFuncAttributeMaxDynamicSharedMemorySize, GEMM_SMEM_BYTES);
        cudaFuncSetAttribute(wo_gemm_kernel,
                             cudaFuncAttributeMaxDynamicSharedMemorySize, GEMM_SMEM_BYTES);
        cudaFuncSetAttribute(flash_tc_kernel,
                             cudaFuncAttributeMaxDynamicSharedMemorySize, ATT_SMEM);
        attr_set = true;
    }

    // lengths from raw key rows (PAD rows are exactly zero)
    len_kernel<<<BATCH, 512>>>(key);

    // input + weight hi/lo splits (fused launches)
    dim3 inGrid((MROWS * HDIM) / (256 * 4), 3);    // (8192, 3)
    dim3 wGrid((HDIM * HDIM) / (256 * 4), 4);      // (1024, 4)
    convert_in_kernel<<<inGrid, 256>>>(query, key, value);
    convert_w_kernel<<<wGrid, 256>>>(Wq, Wk, Wv, Wo);

    // QKV projections, fused in one launch (split bf16 epilogue)
    dim3 qkvGrid(HDIM / 128, MROWS / 128, 3);      // (8, 64, 3)
    qkv_gemm_kernel<<<qkvGrid, 128, GEMM_SMEM_BYTES>>>();

    // attention (tensor cores), writes A split directly
    dim3 flashGrid(S_LEN / 128, BATCH * NHEAD);    // (16, 64)
    flash_tc_kernel<<<flashGrid, 256, ATT_SMEM>>>();

    // output projection
    dim3 gemmGrid(HDIM / 128, MROWS / 128);        // (8, 64)
    wo_gemm_kernel<<<gemmGrid, 128, GEMM_SMEM_BYTES>>>(out);
}